// round 3
// baseline (speedup 1.0000x reference)
#include <cuda_runtime.h>

// ---------------- problem constants (fixed shapes per reference) ----------------
#define Bq 2
#define Hq 16
#define Sq 4096
#define DK 128
#define DV 256
#define LC 64
#define NCHUNK (Sq / LC)        // 64
#define BHN (Bq * Hq)           // 32
#define NCG (BHN * NCHUNK)      // 2048
#define NROWS (BHN * Sq)        // 131072
#define QSCALE 0.08838834764831845f   // 128^-0.5
#define EPSN 1e-6f
#define OUT_ELEMS ((size_t)NROWS * DV)          // 33,554,432
#define ST_ELEMS  ((size_t)BHN * DK * DV)       // 1,048,576

// ---------------- scratch (static device globals; allocation-free) ----------------
__device__ float g_qs[(size_t)NROWS * DK];   // normalized q * exp(gcum) * SCALE
__device__ float g_kg[(size_t)NROWS * DK];   // normalized k * exp(gcum)
__device__ float g_W [(size_t)NROWS * DK];   // T @ k_gated
__device__ float g_T [(size_t)NCG * LC * LC];
__device__ float g_Aq[(size_t)NCG * LC * LC];
__device__ float g_gexp[(size_t)NROWS];
__device__ float g_decay[NCG];

// ---------------- stage 1 ----------------
#define QK_STR 132   // 128 + 4 pad (float4-aligned, bank-staggered)
#define TT_STR 68    // 64 + 4 pad

extern "C" __global__ void __launch_bounds__(256, 2)
gdn_stage1(const float* __restrict__ q, const float* __restrict__ k,
           const float* __restrict__ g, const float* __restrict__ beta)
{
    extern __shared__ float sh[];
    float* sq   = sh;                        // LC * QK_STR
    float* sk   = sq + LC * QK_STR;          // LC * QK_STR
    float* sA   = sk + LC * QK_STR;          // LC * TT_STR
    float* sT   = sA + LC * TT_STR;          // LC * TT_STR
    float* gcum = sT + LC * TT_STR;          // LC
    float* gexp = gcum + LC;                 // LC
    float* bta  = gexp + LC;                 // LC

    const int cg   = blockIdx.x;
    const int bh   = cg / NCHUNK;
    const int cc   = cg % NCHUNK;
    const int row0 = bh * Sq + cc * LC;
    const int tid  = threadIdx.x;

    if (tid < LC) bta[tid] = beta[row0 + tid];
    if (tid == 0) {
        float s = 0.f;
        for (int i = 0; i < LC; i++) {
            s += g[row0 + i];
            gcum[i] = s;
            gexp[i] = expf(s);
        }
        g_decay[cg] = expf(s);
    }
    __syncthreads();

    // load + L2-normalize q,k (4 threads per row)
    {
        const int r = tid >> 2, lane = tid & 3;
        const float4* qr = (const float4*)(q + (size_t)(row0 + r) * DK) + lane * 8;
        const float4* kr = (const float4*)(k + (size_t)(row0 + r) * DK) + lane * 8;
        float4 qv[8], kv[8];
        float sq2 = 0.f, sk2 = 0.f;
#pragma unroll
        for (int u = 0; u < 8; u++) {
            qv[u] = qr[u]; kv[u] = kr[u];
            sq2 += qv[u].x*qv[u].x + qv[u].y*qv[u].y + qv[u].z*qv[u].z + qv[u].w*qv[u].w;
            sk2 += kv[u].x*kv[u].x + kv[u].y*kv[u].y + kv[u].z*kv[u].z + kv[u].w*kv[u].w;
        }
        sq2 += __shfl_xor_sync(0xffffffffu, sq2, 1);
        sq2 += __shfl_xor_sync(0xffffffffu, sq2, 2);
        sk2 += __shfl_xor_sync(0xffffffffu, sk2, 1);
        sk2 += __shfl_xor_sync(0xffffffffu, sk2, 2);
        const float qi = 1.f / (sqrtf(sq2) + EPSN);
        const float ki = 1.f / (sqrtf(sk2) + EPSN);
        float4* dq = (float4*)(sq + r * QK_STR + lane * 32);
        float4* dk = (float4*)(sk + r * QK_STR + lane * 32);
#pragma unroll
        for (int u = 0; u < 8; u++) {
            float4 a = qv[u]; a.x *= qi; a.y *= qi; a.z *= qi; a.w *= qi; dq[u] = a;
            float4 b = kv[u]; b.x *= ki; b.y *= ki; b.z *= ki; b.w *= ki; dk[u] = b;
        }
    }
    __syncthreads();

    // A[i][j] = beta_i * (k_i . k_j) * exp(gcum_j - gcum_i), j < i ; also zero T
    for (int idx = tid; idx < LC * LC; idx += 256) {
        const int i = idx >> 6, j = idx & 63;
        sT[i * TT_STR + j] = 0.f;
        if (j < i) {
            const float4* a = (const float4*)(sk + i * QK_STR);
            const float4* b = (const float4*)(sk + j * QK_STR);
            float dot = 0.f;
#pragma unroll
            for (int u = 0; u < 32; u++) {
                float4 x = a[u], y = b[u];
                dot += x.x*y.x + x.y*y.y + x.z*y.z + x.w*y.w;
            }
            sA[i * TT_STR + j] = bta[i] * dot * expf(gcum[j] - gcum[i]);
        }
    }
    __syncthreads();

    // threads 0..63: forward substitution T = A^-1 diag(beta)  (A unit-lower-tri)
    // threads 64..255: Aq[i][j] = SCALE * (q_i . k_j) * exp(gcum_j - gcum_i), j <= i
    if (tid < LC) {
        const int j = tid;
        sT[j * TT_STR + j] = bta[j];
        for (int i = j + 1; i < LC; i++) {
            float s = 0.f;
            for (int m = j; m < i; m++) s -= sA[i * TT_STR + m] * sT[m * TT_STR + j];
            sT[i * TT_STR + j] = s;
        }
    } else {
        for (int idx = tid - 64; idx < LC * LC; idx += 192) {
            const int i = idx >> 6, j = idx & 63;
            float val = 0.f;
            if (j <= i) {
                const float4* a = (const float4*)(sq + i * QK_STR);
                const float4* b = (const float4*)(sk + j * QK_STR);
                float dot = 0.f;
#pragma unroll
                for (int u = 0; u < 32; u++) {
                    float4 x = a[u], y = b[u];
                    dot += x.x*y.x + x.y*y.y + x.z*y.z + x.w*y.w;
                }
                val = QSCALE * dot * expf(gcum[j] - gcum[i]);
            }
            g_Aq[(size_t)cg * (LC * LC) + idx] = val;
        }
    }
    __syncthreads();

    // write T to global
    for (int i4 = tid; i4 < LC * LC / 4; i4 += 256) {
        const int i = i4 >> 4, j4 = i4 & 15;
        *(float4*)(g_T + (size_t)cg * (LC * LC) + i * LC + j4 * 4) =
            *(const float4*)(sT + i * TT_STR + j4 * 4);
    }
    // scale rows: qs = qn*gexp*SCALE (global), kg = kn*gexp (global + in-place shared)
    {
        const int r = tid >> 2, lane = tid & 3;
        const float ge = gexp[r];
        const float qf = ge * QSCALE;
        float4* pq = (float4*)(sq + r * QK_STR + lane * 32);
        float4* pk = (float4*)(sk + r * QK_STR + lane * 32);
        float4* oq = (float4*)(g_qs + (size_t)(row0 + r) * DK) + lane * 8;
        float4* ok = (float4*)(g_kg + (size_t)(row0 + r) * DK) + lane * 8;
#pragma unroll
        for (int u = 0; u < 8; u++) {
            float4 a = pq[u]; a.x *= qf; a.y *= qf; a.z *= qf; a.w *= qf; oq[u] = a;
            float4 b = pk[u]; b.x *= ge; b.y *= ge; b.z *= ge; b.w *= ge; pk[u] = b; ok[u] = b;
        }
        if (lane == 0) g_gexp[row0 + r] = ge;
    }
    __syncthreads();

    // W = T @ k_gated  (64x64 * 64x128)
    {
        const int colg = tid & 31;       // 4-col group
        const int rowg = tid >> 5;       // 0..7 ; rows rowg + 8u
        float4 acc[8];
#pragma unroll
        for (int u = 0; u < 8; u++) acc[u] = make_float4(0.f, 0.f, 0.f, 0.f);
        for (int m = 0; m < LC; m++) {
            const float4 b = *(const float4*)(sk + m * QK_STR + colg * 4);
#pragma unroll
            for (int u = 0; u < 8; u++) {
                const float a = sT[(rowg + 8 * u) * TT_STR + m];
                acc[u].x += a * b.x; acc[u].y += a * b.y;
                acc[u].z += a * b.z; acc[u].w += a * b.w;
            }
        }
#pragma unroll
        for (int u = 0; u < 8; u++)
            *(float4*)(g_W + (size_t)(row0 + rowg + 8 * u) * DK + colg * 4) = acc[u];
    }
}

// ---------------- stage 2 : sequential scan over chunks ----------------
#define VT 32
#define NT (DV / VT)   // 8
#define SSTR 36
#define CSTR 36
#define ASTR 68
#define BSTR 132

extern "C" __global__ void __launch_bounds__(256, 2)
gdn_stage2(const float* __restrict__ v, float* __restrict__ out, const int write_state)
{
    extern __shared__ float sh[];
    float* sS  = sh;                   // DK * SSTR  (state tile, 128 x 32)
    float* sC  = sS + DK * SSTR;       // LC * CSTR  (correction, 64 x 32)
    float* sV  = sC + LC * CSTR;       // LC * CSTR  (v_gated tile)
    float* sbA = sV + LC * CSTR;       // LC * ASTR  (T / Aq staging)
    float* sbB = sbA + LC * ASTR;      // LC * BSTR  (W / qs / kg staging)

    const int bx   = blockIdx.x;
    const int bh   = bx / NT;
    const int tile = bx % NT;
    const int tid  = threadIdx.x;
    const int colg = tid & 7;          // 4-col group within the 32-col tile
    const int rowg = tid >> 3;         // 0..31
    const int c4   = colg * 4;
    const int vcol0 = tile * VT;

    for (int idx = tid; idx < DK * VT; idx += 256)
        sS[(idx >> 5) * SSTR + (idx & 31)] = 0.f;
    __syncthreads();

    for (int cc = 0; cc < NCHUNK; cc++) {
        const int cg   = bh * NCHUNK + cc;
        const int row0 = bh * Sq + cc * LC;
        const float* Tg  = g_T  + (size_t)cg * (LC * LC);
        const float* Aqg = g_Aq + (size_t)cg * (LC * LC);

        // ---- stage T -> sbA, W -> sbB, v*gexp -> sV
        for (int i4 = tid; i4 < LC * LC / 4; i4 += 256) {
            const int i = i4 >> 4, j4 = i4 & 15;
            *(float4*)(sbA + i * ASTR + j4 * 4) = *(const float4*)(Tg + i * LC + j4 * 4);
        }
        for (int i4 = tid; i4 < LC * DK / 4; i4 += 256) {
            const int i = i4 >> 5, j4 = i4 & 31;
            *(float4*)(sbB + i * BSTR + j4 * 4) =
                *(const float4*)(g_W + (size_t)(row0 + i) * DK + j4 * 4);
        }
        for (int i4 = tid; i4 < LC * VT / 4; i4 += 256) {
            const int i = i4 >> 3, j4 = i4 & 7;
            const float ge = g_gexp[row0 + i];
            float4 vv = *(const float4*)(v + (size_t)(row0 + i) * DV + vcol0 + j4 * 4);
            vv.x *= ge; vv.y *= ge; vv.z *= ge; vv.w *= ge;
            *(float4*)(sV + i * CSTR + j4 * 4) = vv;
        }
        __syncthreads();

        // ---- corr = T @ Vg  -  W @ S   (rows rowg, rowg+32)
        float4 u0 = make_float4(0.f,0.f,0.f,0.f), u1 = u0;
        for (int m = 0; m < LC; m++) {
            const float4 b = *(const float4*)(sV + m * CSTR + c4);
            const float a0 = sbA[rowg * ASTR + m];
            const float a1 = sbA[(rowg + 32) * ASTR + m];
            u0.x += a0*b.x; u0.y += a0*b.y; u0.z += a0*b.z; u0.w += a0*b.w;
            u1.x += a1*b.x; u1.y += a1*b.y; u1.z += a1*b.z; u1.w += a1*b.w;
        }
        for (int m = 0; m < DK; m++) {
            const float4 b = *(const float4*)(sS + m * SSTR + c4);
            const float a0 = sbB[rowg * BSTR + m];
            const float a1 = sbB[(rowg + 32) * BSTR + m];
            u0.x -= a0*b.x; u0.y -= a0*b.y; u0.z -= a0*b.z; u0.w -= a0*b.w;
            u1.x -= a1*b.x; u1.y -= a1*b.y; u1.z -= a1*b.z; u1.w -= a1*b.w;
        }
        *(float4*)(sC + rowg * CSTR + c4) = u0;
        *(float4*)(sC + (rowg + 32) * CSTR + c4) = u1;
        __syncthreads();

        // ---- stage qs -> sbB, Aq -> sbA
        for (int i4 = tid; i4 < LC * LC / 4; i4 += 256) {
            const int i = i4 >> 4, j4 = i4 & 15;
            *(float4*)(sbA + i * ASTR + j4 * 4) = *(const float4*)(Aqg + i * LC + j4 * 4);
        }
        for (int i4 = tid; i4 < LC * DK / 4; i4 += 256) {
            const int i = i4 >> 5, j4 = i4 & 31;
            *(float4*)(sbB + i * BSTR + j4 * 4) =
                *(const float4*)(g_qs + (size_t)(row0 + i) * DK + j4 * 4);
        }
        __syncthreads();

        // ---- O = qs @ S + Aq @ corr  (written straight to gmem)
        float4 o0 = make_float4(0.f,0.f,0.f,0.f), o1 = o0;
        for (int m = 0; m < DK; m++) {
            const float4 b = *(const float4*)(sS + m * SSTR + c4);
            const float a0 = sbB[rowg * BSTR + m];
            const float a1 = sbB[(rowg + 32) * BSTR + m];
            o0.x += a0*b.x; o0.y += a0*b.y; o0.z += a0*b.z; o0.w += a0*b.w;
            o1.x += a1*b.x; o1.y += a1*b.y; o1.z += a1*b.z; o1.w += a1*b.w;
        }
        for (int m = 0; m < LC; m++) {
            const float4 b = *(const float4*)(sC + m * CSTR + c4);
            const float a0 = sbA[rowg * ASTR + m];
            const float a1 = sbA[(rowg + 32) * ASTR + m];
            o0.x += a0*b.x; o0.y += a0*b.y; o0.z += a0*b.z; o0.w += a0*b.w;
            o1.x += a1*b.x; o1.y += a1*b.y; o1.z += a1*b.z; o1.w += a1*b.w;
        }
        *(float4*)(out + (size_t)(row0 + rowg) * DV + vcol0 + c4) = o0;
        *(float4*)(out + (size_t)(row0 + rowg + 32) * DV + vcol0 + c4) = o1;
        __syncthreads();

        // ---- stage kg -> sbB
        for (int i4 = tid; i4 < LC * DK / 4; i4 += 256) {
            const int i = i4 >> 5, j4 = i4 & 31;
            *(float4*)(sbB + i * BSTR + j4 * 4) =
                *(const float4*)(g_kg + (size_t)(row0 + i) * DK + j4 * 4);
        }
        __syncthreads();

        // ---- S = decay*S + kg^T @ corr   (rows rowg+{0,32,64,96} of 128)
        float4 s0 = make_float4(0.f,0.f,0.f,0.f), s1 = s0, s2 = s0, s3 = s0;
        for (int i = 0; i < LC; i++) {
            const float4 b = *(const float4*)(sC + i * CSTR + c4);
            const float k0 = sbB[i * BSTR + rowg];
            const float k1 = sbB[i * BSTR + rowg + 32];
            const float k2 = sbB[i * BSTR + rowg + 64];
            const float k3 = sbB[i * BSTR + rowg + 96];
            s0.x += k0*b.x; s0.y += k0*b.y; s0.z += k0*b.z; s0.w += k0*b.w;
            s1.x += k1*b.x; s1.y += k1*b.y; s1.z += k1*b.z; s1.w += k1*b.w;
            s2.x += k2*b.x; s2.y += k2*b.y; s2.z += k2*b.z; s2.w += k2*b.w;
            s3.x += k3*b.x; s3.y += k3*b.y; s3.z += k3*b.z; s3.w += k3*b.w;
        }
        const float dec = g_decay[cg];
        {
            float4* p; float4 cur;
            p = (float4*)(sS + rowg * SSTR + c4);          cur = *p;
            cur.x = cur.x*dec + s0.x; cur.y = cur.y*dec + s0.y;
            cur.z = cur.z*dec + s0.z; cur.w = cur.w*dec + s0.w; *p = cur;
            p = (float4*)(sS + (rowg + 32) * SSTR + c4);   cur = *p;
            cur.x = cur.x*dec + s1.x; cur.y = cur.y*dec + s1.y;
            cur.z = cur.z*dec + s1.z; cur.w = cur.w*dec + s1.w; *p = cur;
            p = (float4*)(sS + (rowg + 64) * SSTR + c4);   cur = *p;
            cur.x = cur.x*dec + s2.x; cur.y = cur.y*dec + s2.y;
            cur.z = cur.z*dec + s2.z; cur.w = cur.w*dec + s2.w; *p = cur;
            p = (float4*)(sS + (rowg + 96) * SSTR + c4);   cur = *p;
            cur.x = cur.x*dec + s3.x; cur.y = cur.y*dec + s3.y;
            cur.z = cur.z*dec + s3.z; cur.w = cur.w*dec + s3.w; *p = cur;
        }
        __syncthreads();
    }

    if (write_state) {
        for (int idx = tid; idx < DK * VT; idx += 256) {
            const int d = idx >> 5, ccl = idx & 31;
            out[OUT_ELEMS + ((size_t)bh * DK + d) * DV + vcol0 + ccl] = sS[d * SSTR + ccl];
        }
    }
}

// ---------------- launch ----------------
extern "C" void kernel_launch(void* const* d_in, const int* in_sizes, int n_in,
                              void* d_out, int out_size)
{
    const float* q    = (const float*)d_in[0];
    const float* k    = (const float*)d_in[1];
    const float* v    = (const float*)d_in[2];
    const float* g    = (const float*)d_in[3];
    const float* beta = (const float*)d_in[4];
    float* out = (float*)d_out;

    const int write_state = ((size_t)out_size >= OUT_ELEMS + ST_ELEMS) ? 1 : 0;

    const int s1_smem = (int)((2 * LC * QK_STR + 2 * LC * TT_STR + 3 * LC) * sizeof(float));
    const int s2_smem = (int)((DK * SSTR + 2 * LC * CSTR + LC * ASTR + LC * BSTR) * sizeof(float));

    cudaFuncSetAttribute((const void*)gdn_stage1,
                         cudaFuncAttributeMaxDynamicSharedMemorySize, s1_smem);
    cudaFuncSetAttribute((const void*)gdn_stage2,
                         cudaFuncAttributeMaxDynamicSharedMemorySize, s2_smem);

    gdn_stage1<<<NCG, 256, s1_smem>>>(q, k, g, beta);
    gdn_stage2<<<BHN * NT, 256, s2_smem>>>(v, out, write_state);
}